// round 4
// baseline (speedup 1.0000x reference)
#include <cuda_runtime.h>
#include <cuda_fp16.h>
#include <float.h>

#define NIMG 32
#define H    512
#define W    512
#define HW   (H * W)
#define CHW  (3 * HW)

#define NEG2 0xFC00FC00u          // half2(-inf, -inf)
#define NBLK (NIMG * 4)           // 128 blocks: 4 row-strips of 128 rows

__device__ float g_partial[NBLK];

__device__ __forceinline__ unsigned hmax2u(unsigned a, unsigned b) {
    __half2 ha = *reinterpret_cast<__half2*>(&a);
    __half2 hb = *reinterpret_cast<__half2*>(&b);
    __half2 hm = __hmax2(ha, hb);
    return *reinterpret_cast<unsigned*>(&hm);
}
__device__ __forceinline__ unsigned sh1(unsigned a, unsigned b) {
    return __byte_perm(a, b, 0x5432);   // (a.hi, b.lo)
}

// ---------------------------------------------------------------------------
// Fused kernel. One block = (image n, strip of 128 output rows), 512 threads.
// Streams hmax rows [base, base+162), base = R0-17, in 11 chunks of 16 rows.
// smem rings: hring (32 hmax rows), tring (48 vertical-5-max rows).
// Per chunk: S1 hpass (warp/row) -> BAR -> S2 v5max -> BAR -> S3 combine+acc.
// ---------------------------------------------------------------------------
__global__ __launch_bounds__(512) void fused_kernel(const float* __restrict__ img) {
    extern __shared__ unsigned sm[];
    unsigned* hring = sm;                       //  32*256 uints (32 KB)
    unsigned* tring = sm + 32 * 256;            //  48*256 uints (48 KB)
    unsigned* s2    = sm + 32 * 256 + 48 * 256; //  16*280
    unsigned* t2    = s2 + 16 * 280;            //  16*280

    const int bx    = blockIdx.x;
    const int n     = bx >> 2;
    const int strip = bx & 3;
    const int R0    = strip << 7;
    const int base  = R0 - 17;
    const float* pimg = img + (size_t)n * CHW;

    const int tid  = threadIdx.x;
    const int wid  = tid >> 5;
    const int lane = tid & 31;
    unsigned* s2w = s2 + wid * 280;
    unsigned* t2w = t2 + wid * 280;

    float acc = 0.0f;

    #pragma unroll 1
    for (int k = 0; k < 11; k++) {
        const int rs = base + (k << 4);

        // ---- Stage 1: horizontal pass for row r = rs + wid ----
        const int r = rs + wid;
        if (r < base + 162) {
            unsigned* hrow = hring + (((r - base) & 31) << 8);
            if ((unsigned)r < H) {
                const float* prow = pimg + (size_t)r * W;
                if (lane < 10) { s2w[lane] = NEG2; s2w[266 + lane] = NEG2; }
                #pragma unroll
                for (int i = 0; i < 4; i++) {
                    const int q = lane + (i << 5);          // px 4q..4q+3
                    const float4 a = ((const float4*)prow)[q];
                    const float4 b = ((const float4*)(prow + HW))[q];
                    const float4 c = ((const float4*)(prow + 2 * HW))[q];
                    float c0 = 1.0f - fminf(a.x, fminf(b.x, c.x));
                    float c1 = 1.0f - fminf(a.y, fminf(b.y, c.y));
                    float c2 = 1.0f - fminf(a.z, fminf(b.z, c.z));
                    float c3 = 1.0f - fminf(a.w, fminf(b.w, c.w));
                    __half2 h01 = __floats2half2_rn(c0, c1);
                    __half2 h23 = __floats2half2_rn(c2, c3);
                    s2w[2 * q + 10] = *reinterpret_cast<unsigned*>(&h01);
                    s2w[2 * q + 11] = *reinterpret_cast<unsigned*>(&h23);
                }
                __syncwarp();
                // width-5 pass
                #pragma unroll
                for (int j = 0; j < 9; j++) {
                    const int i = lane + (j << 5);
                    if (i < 273) {
                        const unsigned A = s2w[i], B = s2w[i + 1], C = s2w[i + 2];
                        t2w[i] = hmax2u(hmax2u(hmax2u(A, sh1(A, B)),
                                               hmax2u(B, sh1(B, C))), C);
                    }
                }
                __syncwarp();
                // 7-tap combine -> hmax row
                #pragma unroll
                for (int j = 0; j < 8; j++) {
                    const int q = lane + (j << 5);
                    unsigned v;
                    v = sh1(t2w[q + 1], t2w[q + 2]);
                    v = hmax2u(v, t2w[q + 4]);
                    v = hmax2u(v, sh1(t2w[q + 6], t2w[q + 7]));
                    v = hmax2u(v, t2w[q + 9]);
                    v = hmax2u(v, sh1(t2w[q + 11], t2w[q + 12]));
                    v = hmax2u(v, t2w[q + 14]);
                    v = hmax2u(v, sh1(t2w[q + 16], t2w[q + 17]));
                    hrow[q] = v;
                }
            } else {
                #pragma unroll
                for (int j = 0; j < 8; j++) hrow[lane + (j << 5)] = NEG2;
            }
        }
        __syncthreads();

        // ---- Stage 2: vertical width-5 max, t[j] = max(h[j..j+4]) ----
        {
            const int jlo = (k == 0) ? base : rs - 4;
            const int jhi = min(rs + 12, base + 158);
            const int j   = jlo + wid;
            if (j < jhi) {
                const int jr = j - base;
                const uint4* h0 = (const uint4*)(hring + (((jr    ) & 31) << 8));
                const uint4* h1 = (const uint4*)(hring + (((jr + 1) & 31) << 8));
                const uint4* h2 = (const uint4*)(hring + (((jr + 2) & 31) << 8));
                const uint4* h3 = (const uint4*)(hring + (((jr + 3) & 31) << 8));
                const uint4* h4 = (const uint4*)(hring + (((jr + 4) & 31) << 8));
                uint4* trow = (uint4*)(tring + ((jr % 48) << 8));
                #pragma unroll
                for (int u = 0; u < 2; u++) {
                    const int q = lane + (u << 5);
                    const uint4 x0 = h0[q], x1 = h1[q], x2 = h2[q],
                                x3 = h3[q], x4 = h4[q];
                    uint4 m;
                    m.x = hmax2u(hmax2u(hmax2u(x0.x, x1.x), hmax2u(x2.x, x3.x)), x4.x);
                    m.y = hmax2u(hmax2u(hmax2u(x0.y, x1.y), hmax2u(x2.y, x3.y)), x4.y);
                    m.z = hmax2u(hmax2u(hmax2u(x0.z, x1.z), hmax2u(x2.z, x3.z)), x4.z);
                    m.w = hmax2u(hmax2u(hmax2u(x0.w, x1.w), hmax2u(x2.w, x3.w)), x4.w);
                    trow[q] = m;
                }
            }
        }
        __syncthreads();

        // ---- Stage 3: 7-tap vertical combine + |.| accumulate ----
        {
            const int olo = max(R0, rs - 17);
            const int ohi = min(R0 + 128, rs - 1);
            const int o   = olo + wid;
            if (o < ohi) {
                const int orb = o - 17 - base;          // >= 0
                const uint4* t0 = (const uint4*)(tring + (((orb     ) % 48) << 8));
                const uint4* t1 = (const uint4*)(tring + (((orb +  5) % 48) << 8));
                const uint4* t3 = (const uint4*)(tring + (((orb + 10) % 48) << 8));
                const uint4* t4 = (const uint4*)(tring + (((orb + 15) % 48) << 8));
                const uint4* t5 = (const uint4*)(tring + (((orb + 20) % 48) << 8));
                const uint4* t6 = (const uint4*)(tring + (((orb + 25) % 48) << 8));
                const uint4* t7 = (const uint4*)(tring + (((orb + 30) % 48) << 8));
                #pragma unroll
                for (int u = 0; u < 2; u++) {
                    const int q = lane + (u << 5);
                    uint4 m = t0[q];
                    uint4 a;
                    a = t1[q]; m.x = hmax2u(m.x, a.x); m.y = hmax2u(m.y, a.y);
                               m.z = hmax2u(m.z, a.z); m.w = hmax2u(m.w, a.w);
                    a = t3[q]; m.x = hmax2u(m.x, a.x); m.y = hmax2u(m.y, a.y);
                               m.z = hmax2u(m.z, a.z); m.w = hmax2u(m.w, a.w);
                    a = t4[q]; m.x = hmax2u(m.x, a.x); m.y = hmax2u(m.y, a.y);
                               m.z = hmax2u(m.z, a.z); m.w = hmax2u(m.w, a.w);
                    a = t5[q]; m.x = hmax2u(m.x, a.x); m.y = hmax2u(m.y, a.y);
                               m.z = hmax2u(m.z, a.z); m.w = hmax2u(m.w, a.w);
                    a = t6[q]; m.x = hmax2u(m.x, a.x); m.y = hmax2u(m.y, a.y);
                               m.z = hmax2u(m.z, a.z); m.w = hmax2u(m.w, a.w);
                    a = t7[q]; m.x = hmax2u(m.x, a.x); m.y = hmax2u(m.y, a.y);
                               m.z = hmax2u(m.z, a.z); m.w = hmax2u(m.w, a.w);
                    const float2 f0 = __half22float2(*reinterpret_cast<__half2*>(&m.x));
                    const float2 f1 = __half22float2(*reinterpret_cast<__half2*>(&m.y));
                    const float2 f2 = __half22float2(*reinterpret_cast<__half2*>(&m.z));
                    const float2 f3 = __half22float2(*reinterpret_cast<__half2*>(&m.w));
                    acc += (f0.x + f0.y) + (f1.x + f1.y)
                         + (f2.x + f2.y) + (f3.x + f3.y);
                }
            }
        }
        __syncthreads();
    }

    // block reduction 512 -> 1
    __shared__ float red[16];
    #pragma unroll
    for (int off = 16; off; off >>= 1)
        acc += __shfl_down_sync(0xffffffffu, acc, off);
    if (lane == 0) red[wid] = acc;
    __syncthreads();
    if (tid < 16) {
        float v = red[tid];
        #pragma unroll
        for (int off = 8; off; off >>= 1)
            v += __shfl_down_sync(0xffffu, v, off);
        if (tid == 0) g_partial[bx] = v;
    }
}

// ---------------------------------------------------------------------------
// Final reduction of 128 partials -> mean
// ---------------------------------------------------------------------------
__global__ __launch_bounds__(128) void finish_kernel(float* __restrict__ out) {
    const int tid = threadIdx.x;
    float v = g_partial[tid];
    __shared__ float red[4];
    #pragma unroll
    for (int off = 16; off; off >>= 1)
        v += __shfl_down_sync(0xffffffffu, v, off);
    if ((tid & 31) == 0) red[tid >> 5] = v;
    __syncthreads();
    if (tid < 4) {
        float x = red[tid];
        #pragma unroll
        for (int off = 2; off; off >>= 1)
            x += __shfl_down_sync(0xfu, x, off);
        if (tid == 0) out[0] = x * (1.0f / ((float)NIMG * (float)HW));
    }
}

// ---------------------------------------------------------------------------
extern "C" void kernel_launch(void* const* d_in, const int* in_sizes, int n_in,
                              void* d_out, int out_size) {
    const float* img = (const float*)d_in[0];
    float* out = (float*)d_out;

    const int smem = (32 * 256 + 48 * 256 + 2 * 16 * 280) * (int)sizeof(unsigned);
    cudaFuncSetAttribute(fused_kernel,
                         cudaFuncAttributeMaxDynamicSharedMemorySize, smem);

    fused_kernel<<<NBLK, 512, smem>>>(img);
    finish_kernel<<<1, 128>>>(out);
}

// round 5
// speedup vs baseline: 1.1088x; 1.1088x over previous
#include <cuda_runtime.h>
#include <cuda_fp16.h>
#include <float.h>

#define NIMG 32
#define H    512
#define W    512
#define HW   (H * W)
#define CHW  (3 * HW)

#define NEG2 0xFC00FC00u          // half2(-inf, -inf)
#define NBLK (NIMG * 4)           // 128 blocks: 4 row-strips of 128 rows

__device__ float g_partial[NBLK];
__device__ int   g_count;         // zero-initialized; reset by last block

__device__ __forceinline__ unsigned hmax2u(unsigned a, unsigned b) {
    __half2 ha = *reinterpret_cast<__half2*>(&a);
    __half2 hb = *reinterpret_cast<__half2*>(&b);
    __half2 hm = __hmax2(ha, hb);
    return *reinterpret_cast<unsigned*>(&hm);
}
__device__ __forceinline__ unsigned sh1(unsigned a, unsigned b) {
    return __byte_perm(a, b, 0x5432);   // (a.hi, b.lo)
}

// ---------------------------------------------------------------------------
// Fused kernel. One block = (image n, strip of 128 output rows), 512 threads.
// Streams hmax rows [base, base+162), base = R0-17, in 11 chunks of 16 rows.
// smem rings: hring (32 hmax rows), tring (48 vertical-5-max rows).
// Per chunk: S1 hpass (from prefetched regs) | prefetch k+1 -> BAR ->
//            S2 v5max -> BAR -> S3 combine+acc -> BAR.
// Prefetch is register-only, so the ring/barrier schedule is unchanged vs R4.
// ---------------------------------------------------------------------------
__global__ __launch_bounds__(512) void fused_kernel(const float* __restrict__ img,
                                                    float* __restrict__ out) {
    extern __shared__ unsigned sm[];
    unsigned* hring = sm;                       //  32*256 uints (32 KB)
    unsigned* tring = sm + 32 * 256;            //  48*256 uints (48 KB)
    unsigned* s2    = sm + 32 * 256 + 48 * 256; //  16*280
    unsigned* t2    = s2 + 16 * 280;            //  16*280

    const int bx    = blockIdx.x;
    const int n     = bx >> 2;
    const int strip = bx & 3;
    const int R0    = strip << 7;
    const int base  = R0 - 17;
    const float* pimg = img + (size_t)n * CHW;

    const int tid  = threadIdx.x;
    const int wid  = tid >> 5;
    const int lane = tid & 31;
    unsigned* s2w = s2 + wid * 280;
    unsigned* t2w = t2 + wid * 280;

    float acc = 0.0f;

    // prefetch registers: chunk row r = base + 16k + wid, 16 px/lane
    float4 pa[4], pb[4], pc[4];
    bool pvalid;

    // prefetch chunk 0
    {
        const int r = base + wid;
        pvalid = (r < base + 162) && ((unsigned)r < H);
        if (pvalid) {
            const float* prow = pimg + (size_t)r * W;
            #pragma unroll
            for (int i = 0; i < 4; i++) {
                const int q = lane + (i << 5);
                pa[i] = ((const float4*)prow)[q];
                pb[i] = ((const float4*)(prow + HW))[q];
                pc[i] = ((const float4*)(prow + 2 * HW))[q];
            }
        }
    }

    #pragma unroll 1
    for (int k = 0; k < 11; k++) {
        const int rs = base + (k << 4);

        // ---- Stage 1: horizontal pass for row r = rs + wid (from regs) ----
        const int r = rs + wid;
        if (r < base + 162) {
            unsigned* hrow = hring + (((r - base) & 31) << 8);
            if (pvalid) {
                if (lane < 10) { s2w[lane] = NEG2; s2w[266 + lane] = NEG2; }
                #pragma unroll
                for (int i = 0; i < 4; i++) {
                    const int q = lane + (i << 5);
                    float c0 = 1.0f - fminf(pa[i].x, fminf(pb[i].x, pc[i].x));
                    float c1 = 1.0f - fminf(pa[i].y, fminf(pb[i].y, pc[i].y));
                    float c2 = 1.0f - fminf(pa[i].z, fminf(pb[i].z, pc[i].z));
                    float c3 = 1.0f - fminf(pa[i].w, fminf(pb[i].w, pc[i].w));
                    __half2 h01 = __floats2half2_rn(c0, c1);
                    __half2 h23 = __floats2half2_rn(c2, c3);
                    s2w[2 * q + 10] = *reinterpret_cast<unsigned*>(&h01);
                    s2w[2 * q + 11] = *reinterpret_cast<unsigned*>(&h23);
                }
                __syncwarp();
                #pragma unroll
                for (int j = 0; j < 9; j++) {
                    const int i = lane + (j << 5);
                    if (i < 273) {
                        const unsigned A = s2w[i], B = s2w[i + 1], C = s2w[i + 2];
                        t2w[i] = hmax2u(hmax2u(hmax2u(A, sh1(A, B)),
                                               hmax2u(B, sh1(B, C))), C);
                    }
                }
                __syncwarp();
                #pragma unroll
                for (int j = 0; j < 8; j++) {
                    const int q = lane + (j << 5);
                    unsigned v;
                    v = sh1(t2w[q + 1], t2w[q + 2]);
                    v = hmax2u(v, t2w[q + 4]);
                    v = hmax2u(v, sh1(t2w[q + 6], t2w[q + 7]));
                    v = hmax2u(v, t2w[q + 9]);
                    v = hmax2u(v, sh1(t2w[q + 11], t2w[q + 12]));
                    v = hmax2u(v, t2w[q + 14]);
                    v = hmax2u(v, sh1(t2w[q + 16], t2w[q + 17]));
                    hrow[q] = v;
                }
            } else {
                #pragma unroll
                for (int j = 0; j < 8; j++) hrow[lane + (j << 5)] = NEG2;
            }
        }

        // ---- Prefetch chunk k+1 (registers only; flies across stages 2/3) ----
        if (k < 10) {
            const int rn = rs + 16 + wid;
            pvalid = (rn < base + 162) && ((unsigned)rn < H);
            if (pvalid) {
                const float* prow = pimg + (size_t)rn * W;
                #pragma unroll
                for (int i = 0; i < 4; i++) {
                    const int q = lane + (i << 5);
                    pa[i] = ((const float4*)prow)[q];
                    pb[i] = ((const float4*)(prow + HW))[q];
                    pc[i] = ((const float4*)(prow + 2 * HW))[q];
                }
            }
        }
        __syncthreads();

        // ---- Stage 2: vertical width-5 max, t[j] = max(h[j..j+4]) ----
        {
            const int jlo = (k == 0) ? base : rs - 4;
            const int jhi = min(rs + 12, base + 158);
            const int j   = jlo + wid;
            if (j < jhi) {
                const int jr = j - base;
                const uint4* h0 = (const uint4*)(hring + (((jr    ) & 31) << 8));
                const uint4* h1 = (const uint4*)(hring + (((jr + 1) & 31) << 8));
                const uint4* h2 = (const uint4*)(hring + (((jr + 2) & 31) << 8));
                const uint4* h3 = (const uint4*)(hring + (((jr + 3) & 31) << 8));
                const uint4* h4 = (const uint4*)(hring + (((jr + 4) & 31) << 8));
                uint4* trow = (uint4*)(tring + ((jr % 48) << 8));
                #pragma unroll
                for (int u = 0; u < 2; u++) {
                    const int q = lane + (u << 5);
                    const uint4 x0 = h0[q], x1 = h1[q], x2 = h2[q],
                                x3 = h3[q], x4 = h4[q];
                    uint4 m;
                    m.x = hmax2u(hmax2u(hmax2u(x0.x, x1.x), hmax2u(x2.x, x3.x)), x4.x);
                    m.y = hmax2u(hmax2u(hmax2u(x0.y, x1.y), hmax2u(x2.y, x3.y)), x4.y);
                    m.z = hmax2u(hmax2u(hmax2u(x0.z, x1.z), hmax2u(x2.z, x3.z)), x4.z);
                    m.w = hmax2u(hmax2u(hmax2u(x0.w, x1.w), hmax2u(x2.w, x3.w)), x4.w);
                    trow[q] = m;
                }
            }
        }
        __syncthreads();

        // ---- Stage 3: 7-tap vertical combine + |.| accumulate ----
        {
            const int olo = max(R0, rs - 17);
            const int ohi = min(R0 + 128, rs - 1);
            const int o   = olo + wid;
            if (o < ohi) {
                const int orb = o - 17 - base;
                const uint4* t0 = (const uint4*)(tring + (((orb     ) % 48) << 8));
                const uint4* t1 = (const uint4*)(tring + (((orb +  5) % 48) << 8));
                const uint4* t3 = (const uint4*)(tring + (((orb + 10) % 48) << 8));
                const uint4* t4 = (const uint4*)(tring + (((orb + 15) % 48) << 8));
                const uint4* t5 = (const uint4*)(tring + (((orb + 20) % 48) << 8));
                const uint4* t6 = (const uint4*)(tring + (((orb + 25) % 48) << 8));
                const uint4* t7 = (const uint4*)(tring + (((orb + 30) % 48) << 8));
                #pragma unroll
                for (int u = 0; u < 2; u++) {
                    const int q = lane + (u << 5);
                    uint4 m = t0[q];
                    uint4 a;
                    a = t1[q]; m.x = hmax2u(m.x, a.x); m.y = hmax2u(m.y, a.y);
                               m.z = hmax2u(m.z, a.z); m.w = hmax2u(m.w, a.w);
                    a = t3[q]; m.x = hmax2u(m.x, a.x); m.y = hmax2u(m.y, a.y);
                               m.z = hmax2u(m.z, a.z); m.w = hmax2u(m.w, a.w);
                    a = t4[q]; m.x = hmax2u(m.x, a.x); m.y = hmax2u(m.y, a.y);
                               m.z = hmax2u(m.z, a.z); m.w = hmax2u(m.w, a.w);
                    a = t5[q]; m.x = hmax2u(m.x, a.x); m.y = hmax2u(m.y, a.y);
                               m.z = hmax2u(m.z, a.z); m.w = hmax2u(m.w, a.w);
                    a = t6[q]; m.x = hmax2u(m.x, a.x); m.y = hmax2u(m.y, a.y);
                               m.z = hmax2u(m.z, a.z); m.w = hmax2u(m.w, a.w);
                    a = t7[q]; m.x = hmax2u(m.x, a.x); m.y = hmax2u(m.y, a.y);
                               m.z = hmax2u(m.z, a.z); m.w = hmax2u(m.w, a.w);
                    const float2 f0 = __half22float2(*reinterpret_cast<__half2*>(&m.x));
                    const float2 f1 = __half22float2(*reinterpret_cast<__half2*>(&m.y));
                    const float2 f2 = __half22float2(*reinterpret_cast<__half2*>(&m.z));
                    const float2 f3 = __half22float2(*reinterpret_cast<__half2*>(&m.w));
                    acc += (f0.x + f0.y) + (f1.x + f1.y)
                         + (f2.x + f2.y) + (f3.x + f3.y);
                }
            }
        }
        __syncthreads();
    }

    // block reduction 512 -> 1
    __shared__ float red[16];
    #pragma unroll
    for (int off = 16; off; off >>= 1)
        acc += __shfl_down_sync(0xffffffffu, acc, off);
    if (lane == 0) red[wid] = acc;
    __syncthreads();
    if (tid < 16) {
        float v = red[tid];
        #pragma unroll
        for (int off = 8; off; off >>= 1)
            v += __shfl_down_sync(0xffffu, v, off);
        if (tid == 0) g_partial[bx] = v;
    }

    // last block reduces all partials (deterministic order) and writes out
    __shared__ bool is_last;
    if (tid == 0) {
        __threadfence();
        is_last = (atomicAdd(&g_count, 1) == NBLK - 1);
    }
    __syncthreads();
    if (is_last && tid < 32) {
        __threadfence();   // acquire partials
        float v = g_partial[tid] + g_partial[tid + 32]
                + g_partial[tid + 64] + g_partial[tid + 96];
        #pragma unroll
        for (int off = 16; off; off >>= 1)
            v += __shfl_down_sync(0xffffffffu, v, off);
        if (tid == 0) {
            out[0] = v * (1.0f / ((float)NIMG * (float)HW));
            g_count = 0;   // reset for next launch/replay
        }
    }
}

// ---------------------------------------------------------------------------
extern "C" void kernel_launch(void* const* d_in, const int* in_sizes, int n_in,
                              void* d_out, int out_size) {
    const float* img = (const float*)d_in[0];
    float* out = (float*)d_out;

    const int smem = (32 * 256 + 48 * 256 + 2 * 16 * 280) * (int)sizeof(unsigned);
    cudaFuncSetAttribute(fused_kernel,
                         cudaFuncAttributeMaxDynamicSharedMemorySize, smem);

    fused_kernel<<<NBLK, 512, smem>>>(img, out);
}

// round 6
// speedup vs baseline: 1.3569x; 1.2237x over previous
#include <cuda_runtime.h>
#include <cuda_fp16.h>
#include <float.h>

#define NIMG 32
#define H    512
#define W    512
#define HW   (H * W)
#define CHW  (3 * HW)

#define NEG2 0xFC00FC00u      // half2(-inf, -inf)

#define SR    32                     // vpass output rows per strip
#define VBLK  (NIMG * 16)            // 512 blocks

__device__ __half g_hmax[NIMG * HW]; // fp16 intermediate (16.75 MB, L2-resident)
__device__ float  g_partial[VBLK];
__device__ int    g_count;           // zero-init; reset by last block

__device__ __forceinline__ unsigned hmax2u(unsigned a, unsigned b) {
    __half2 ha = *reinterpret_cast<__half2*>(&a);
    __half2 hb = *reinterpret_cast<__half2*>(&b);
    __half2 hm = __hmax2(ha, hb);
    return *reinterpret_cast<unsigned*>(&hm);
}
__device__ __forceinline__ unsigned sh1(unsigned a, unsigned b) {
    return __byte_perm(a, b, 0x5432);   // (a.hi, b.lo)
}

// ---------------------------------------------------------------------------
// Kernel 1 (unchanged from R3, measured 21.5us @ 62% DRAM):
// c = 1 - min3(channels) -> fp16, horizontal 35-wide sliding max, packed half2.
// ---------------------------------------------------------------------------
__global__ __launch_bounds__(128) void hpass_kernel(const float* __restrict__ img) {
    const int row = blockIdx.x;
    const int n   = row >> 9;
    const int h   = row & (H - 1);
    const float* p = img + (size_t)n * CHW + (size_t)h * W;

    __shared__ unsigned s2[276];   // px -20 .. 531
    __shared__ unsigned t2[276];

    const int tid = threadIdx.x;

    if (tid < 20) s2[tid < 10 ? tid : 256 + tid] = NEG2;

    const float4 a = ((const float4*)p)[tid];
    const float4 b = ((const float4*)(p + HW))[tid];
    const float4 c = ((const float4*)(p + 2 * HW))[tid];
    float c0 = 1.0f - fminf(a.x, fminf(b.x, c.x));
    float c1 = 1.0f - fminf(a.y, fminf(b.y, c.y));
    float c2 = 1.0f - fminf(a.z, fminf(b.z, c.z));
    float c3 = 1.0f - fminf(a.w, fminf(b.w, c.w));
    __half2 h01 = __floats2half2_rn(c0, c1);
    __half2 h23 = __floats2half2_rn(c2, c3);
    s2[2 * tid + 10] = *reinterpret_cast<unsigned*>(&h01);
    s2[2 * tid + 11] = *reinterpret_cast<unsigned*>(&h23);
    __syncthreads();

    #pragma unroll
    for (int i = tid; i < 273; i += 128) {
        const unsigned A = s2[i], B = s2[i + 1], C = s2[i + 2];
        t2[i] = hmax2u(hmax2u(hmax2u(A, sh1(A, B)), hmax2u(B, sh1(B, C))), C);
    }
    __syncthreads();

    unsigned* orow = (unsigned*)(g_hmax + (size_t)row * W);
    #pragma unroll
    for (int q = tid; q < 256; q += 128) {
        unsigned v;
        v = sh1(t2[q + 1], t2[q + 2]);
        v = hmax2u(v, t2[q + 4]);
        v = hmax2u(v, sh1(t2[q + 6], t2[q + 7]));
        v = hmax2u(v, t2[q + 9]);
        v = hmax2u(v, sh1(t2[q + 11], t2[q + 12]));
        v = hmax2u(v, t2[q + 14]);
        v = hmax2u(v, sh1(t2[q + 16], t2[q + 17]));
        orow[q] = v;
    }
}

// ---------------------------------------------------------------------------
// Kernel 2: vertical 35-tall max + mean, all in registers (no smem, no BAR).
// Block = (image n, 32-row strip). Thread = one half2 column (256 thr = 512 px).
// Bricks of 5 t-rows; t[j'] = max(s[j'..j'+4]); ring tb[7][5] holds bricks
// c-6..c; output o' = 5(c-6)+m = max over the 7 ring slots at offset m.
// Fully unrolled (13 bricks) -> all register indices static.
// Last block reduces g_partial and writes out (fence+counter).
// ---------------------------------------------------------------------------
__global__ __launch_bounds__(256) void vpass_kernel(float* __restrict__ out) {
    const int bx = blockIdx.x;
    const int n  = bx >> 4;
    const int st = bx & 15;
    const int r0 = st << 5;
    const int tid = threadIdx.x;

    const unsigned* base = (const unsigned*)(g_hmax + (size_t)n * HW);
    const int rbase = r0 - 17;

    unsigned s[9];
    unsigned tb[7][5];
    float acc = 0.0f;

    #pragma unroll
    for (int i = 0; i < 4; i++) {
        const int row = rbase + i;
        s[i] = ((unsigned)row < H) ? base[row * 256 + tid] : NEG2;
    }

    #pragma unroll
    for (int c = 0; c < 13; c++) {
        #pragma unroll
        for (int i = 4; i < 9; i++) {
            const int row = rbase + 5 * c + i;
            s[i] = ((unsigned)row < H) ? base[row * 256 + tid] : NEG2;
        }
        // all 5 windows share s[4]: prefix down from s4, suffix up from s4
        const unsigned pre3 = hmax2u(s[4], s[3]);
        const unsigned pre2 = hmax2u(pre3, s[2]);
        const unsigned pre1 = hmax2u(pre2, s[1]);
        const unsigned pre0 = hmax2u(pre1, s[0]);
        const unsigned suf5 = hmax2u(s[4], s[5]);
        const unsigned suf6 = hmax2u(suf5, s[6]);
        const unsigned suf7 = hmax2u(suf6, s[7]);
        const unsigned suf8 = hmax2u(suf7, s[8]);
        unsigned* t = tb[c % 7];
        t[0] = pre0;
        t[1] = hmax2u(pre1, suf5);
        t[2] = hmax2u(pre2, suf6);
        t[3] = hmax2u(pre3, suf7);
        t[4] = suf8;

        if (c >= 6) {
            #pragma unroll
            for (int m = 0; m < 5; m++) {
                if (c < 12 || m < 2) {          // last brick emits o'=30,31 only
                    unsigned v = tb[0][m];
                    v = hmax2u(v, tb[1][m]);
                    v = hmax2u(v, tb[2][m]);
                    v = hmax2u(v, tb[3][m]);
                    v = hmax2u(v, tb[4][m]);
                    v = hmax2u(v, tb[5][m]);
                    v = hmax2u(v, tb[6][m]);
                    const float2 f = __half22float2(*reinterpret_cast<__half2*>(&v));
                    acc += fabsf(f.x) + fabsf(f.y);
                }
            }
        }
        s[0] = s[5]; s[1] = s[6]; s[2] = s[7]; s[3] = s[8];
    }

    // block reduction 256 -> 1
    __shared__ float red[8];
    const int lane = tid & 31;
    #pragma unroll
    for (int off = 16; off; off >>= 1)
        acc += __shfl_down_sync(0xffffffffu, acc, off);
    if (lane == 0) red[tid >> 5] = acc;
    __syncthreads();
    if (tid < 8) {
        float v = red[tid];
        #pragma unroll
        for (int off = 4; off; off >>= 1)
            v += __shfl_down_sync(0xffu, v, off);
        if (tid == 0) g_partial[bx] = v;
    }

    // last block: deterministic final reduce + write
    __shared__ bool is_last;
    if (tid == 0) {
        __threadfence();
        is_last = (atomicAdd(&g_count, 1) == VBLK - 1);
    }
    __syncthreads();
    if (is_last) {
        __threadfence();
        float v = g_partial[tid] + g_partial[tid + 256];
        #pragma unroll
        for (int off = 16; off; off >>= 1)
            v += __shfl_down_sync(0xffffffffu, v, off);
        if (lane == 0) red[tid >> 5] = v;
        __syncthreads();
        if (tid < 8) {
            float x = red[tid];
            #pragma unroll
            for (int off = 4; off; off >>= 1)
                x += __shfl_down_sync(0xffu, x, off);
            if (tid == 0) {
                out[0] = x * (1.0f / ((float)NIMG * (float)HW));
                g_count = 0;   // reset for graph replay
            }
        }
    }
}

// ---------------------------------------------------------------------------
extern "C" void kernel_launch(void* const* d_in, const int* in_sizes, int n_in,
                              void* d_out, int out_size) {
    const float* img = (const float*)d_in[0];
    float* out = (float*)d_out;

    hpass_kernel<<<NIMG * H, 128>>>(img);
    vpass_kernel<<<VBLK, 256>>>(out);
}